// round 6
// baseline (speedup 1.0000x reference)
#include <cuda_runtime.h>
#include <cstdint>
#include <math.h>

// ---------------- problem constants ----------------
#define NBS   2
#define NR    512
#define NROI  (NBS*NR)          // 1024
#define CH    256
#define OUTS  7
#define NPIX  (OUTS*OUTS)       // 49
#define FDIM  (CH*NPIX)         // 12544
#define DDIM  1024
#define NCLS  81
#define NREG  320
#define KS1   4                 // split-K for fc1
#define KS2   2                 // split-K for fc2

// ---------------- device scratch ----------------
// NOTE: all GEMM K-dims are stored with a within-8 interleave perm
// [0,4,1,5,2,6,3,7] so mma fragment pairs (k, k+4) are contiguous (LDS.64).
__device__ float g_X[(size_t)NROI * FDIM];      // pooled features, K-permuted
__device__ float g_Y[(size_t)NROI * DDIM];      // fc1 out, K-permuted (fc2's A)
__device__ float g_Z[(size_t)NROI * DDIM];      // fc2 out, natural
__device__ float g_W1r[(size_t)DDIM * FDIM];    // tf32 W1, K-permuted
__device__ float g_W2r[(size_t)DDIM * DDIM];    // tf32 W2, K-permuted
__device__ float g_P[(size_t)KS1 * NROI * DDIM]; // split-K partials (16MB)
__device__ int   g_lvl[NROI];
__device__ float g_meta[NROI * 4];

// ---------------- helpers ----------------
__device__ __forceinline__ float tf32_rna(float x) {
    uint32_t r; asm("cvt.rna.tf32.f32 %0, %1;" : "=r"(r) : "f"(x));
    return __uint_as_float(r);
}
__device__ __forceinline__ int permk(int k) {   // within-8 interleave
    int r = k & 7;
    return (k & ~7) | ((r < 4) ? (r << 1) : (((r - 4) << 1) | 1));
}
__device__ __forceinline__ uint32_t smem_u32(const void* p) {
    uint32_t a;
    asm("{ .reg .u64 t; cvta.to.shared.u64 t, %1; cvt.u32.u64 %0, t; }" : "=r"(a) : "l"(p));
    return a;
}
#define CP16(dst, src) \
    asm volatile("cp.async.cg.shared.global [%0], [%1], 16;" :: "r"(dst), "l"(src) : "memory")
#define CPCOMMIT() asm volatile("cp.async.commit_group;" ::: "memory")
#define CPWAIT2()  asm volatile("cp.async.wait_group 2;" ::: "memory")

__device__ __forceinline__ void mma_tf32(float c[4], const uint32_t a[4], const uint32_t b[2]) {
    asm volatile(
        "mma.sync.aligned.m16n8k8.row.col.f32.tf32.tf32.f32 "
        "{%0,%1,%2,%3}, {%4,%5,%6,%7}, {%8,%9}, {%0,%1,%2,%3};"
        : "+f"(c[0]), "+f"(c[1]), "+f"(c[2]), "+f"(c[3])
        : "r"(a[0]), "r"(a[1]), "r"(a[2]), "r"(a[3]), "r"(b[0]), "r"(b[1]));
}

// ---------------- roi prep ----------------
__global__ void roi_prep_kernel(const float* __restrict__ rois) {
    int i = blockIdx.x * blockDim.x + threadIdx.x;
    if (i >= NROI) return;
    float x1 = rois[i * 4 + 0], y1 = rois[i * 4 + 1];
    float x2 = rois[i * 4 + 2], y2 = rois[i * 4 + 3];
    float w = x2 - x1, h = y2 - y1;
    float lv = floorf(4.0f + log2f(sqrtf(w * h) / 224.0f + 1e-6f));
    int li = (int)lv - 2;
    g_lvl[i] = li;
    int lic = li < 0 ? 0 : (li > 3 ? 3 : li);
    float scale = 1.0f / (float)(4 << lic);
    float x1s = x1 * scale, y1s = y1 * scale;
    float rw = fmaxf(x2 * scale - x1s, 1.0f);
    float rh = fmaxf(y2 * scale - y1s, 1.0f);
    g_meta[i * 4 + 0] = x1s;
    g_meta[i * 4 + 1] = y1s;
    g_meta[i * 4 + 2] = rw / (float)OUTS;
    g_meta[i * 4 + 3] = rh / (float)OUTS;
}

// ---------------- roi align: 8 channels/thread, branch-free gathers ----------
__global__ void __launch_bounds__(256)
roi_align_kernel(const float* __restrict__ f2, const float* __restrict__ f3,
                 const float* __restrict__ f4, const float* __restrict__ f5) {
    int idx = blockIdx.x * blockDim.x + threadIdx.x;
    if (idx >= NROI * (CH / 8) * NPIX) return;
    int n   = idx / ((CH / 8) * NPIX);
    int rem = idx - n * ((CH / 8) * NPIX);
    int c8  = rem / NPIX;
    int p   = rem - c8 * NPIX;
    int c0  = c8 * 8;

    size_t nbase = (size_t)n * FDIM;

    int li = g_lvl[n];
    if (li < 0 || li > 3) {
        #pragma unroll
        for (int c = 0; c < 8; c++)
            g_X[nbase + permk((c0 + c) * NPIX + p)] = 0.0f;
        return;
    }

    int ph = p / OUTS, pw = p - ph * OUTS;
    const float* f; int H;
    if      (li == 0) { f = f2; H = 200; }
    else if (li == 1) { f = f3; H = 100; }
    else if (li == 2) { f = f4; H = 50;  }
    else              { f = f5; H = 25;  }
    int W = H;
    int HW = H * W;
    int b = (n >= NR) ? 1 : 0;
    const float* base = f + ((size_t)b * CH + c0) * (size_t)HW;

    float x1 = g_meta[n * 4 + 0], y1 = g_meta[n * 4 + 1];
    float bw = g_meta[n * 4 + 2], bh = g_meta[n * 4 + 3];

    int yo0[2], yo1[2]; float lys[2]; float vyf[2];
    int xo0[2], xo1[2]; float lxs[2]; float vxf[2];
    #pragma unroll
    for (int i = 0; i < 2; i++) {
        float y = y1 + ((float)ph + 0.25f + 0.5f * (float)i) * bh;
        vyf[i] = ((y > -1.0f) && (y < (float)H)) ? 1.0f : 0.0f;
        float yc = fminf(fmaxf(y, 0.0f), (float)(H - 1));
        float y0f = floorf(yc);
        int y0 = (int)y0f;
        yo0[i] = y0 * W;
        yo1[i] = min(y0 + 1, H - 1) * W;
        lys[i] = yc - y0f;

        float x = x1 + ((float)pw + 0.25f + 0.5f * (float)i) * bw;
        vxf[i] = ((x > -1.0f) && (x < (float)W)) ? 1.0f : 0.0f;
        float xc = fminf(fmaxf(x, 0.0f), (float)(W - 1));
        float x0f = floorf(xc);
        xo0[i] = (int)x0f;
        xo1[i] = min((int)x0f + 1, W - 1);
        lxs[i] = xc - x0f;
    }

    int   off[16];
    float wgt[16];
    #pragma unroll
    for (int iy = 0; iy < 2; iy++) {
        #pragma unroll
        for (int ix = 0; ix < 2; ix++) {
            float v = vyf[iy] * vxf[ix];
            float ly = lys[iy], lx = lxs[ix];
            int s = (iy * 2 + ix) * 4;
            off[s + 0] = yo0[iy] + xo0[ix]; wgt[s + 0] = v * (1.0f - ly) * (1.0f - lx);
            off[s + 1] = yo0[iy] + xo1[ix]; wgt[s + 1] = v * (1.0f - ly) * lx;
            off[s + 2] = yo1[iy] + xo0[ix]; wgt[s + 2] = v * ly * (1.0f - lx);
            off[s + 3] = yo1[iy] + xo1[ix]; wgt[s + 3] = v * ly * lx;
        }
    }

    #pragma unroll
    for (int c = 0; c < 8; c++) {
        const float* bc = base + (size_t)c * HW;
        float v[16];
        #pragma unroll
        for (int q = 0; q < 16; q++) v[q] = bc[off[q]];
        float acc = 0.0f;
        #pragma unroll
        for (int q = 0; q < 16; q++) acc = fmaf(wgt[q], v[q], acc);
        g_X[nbase + permk((c0 + c) * NPIX + p)] = tf32_rna(acc * 0.25f);
    }
}

// ---------------- tf32 round + K-permute (weights): one 8-block per thread ----
#define N8W1 (DDIM * FDIM / 8)
#define N8W2 (DDIM * DDIM / 8)
__global__ void round_all_kernel(const float4* __restrict__ w1,
                                 const float4* __restrict__ w2) {
    int i = blockIdx.x * blockDim.x + threadIdx.x;
    const float4* in; float4* out; int j;
    if (i < N8W1) { in = w1; out = (float4*)g_W1r; j = i; }
    else if (i < N8W1 + N8W2) { in = w2; out = (float4*)g_W2r; j = i - N8W1; }
    else return;
    float4 lo = in[2 * j], hi = in[2 * j + 1];
    float4 o0, o1;  // interleave [f0,f4,f1,f5] [f2,f6,f3,f7]
    o0.x = tf32_rna(lo.x); o0.y = tf32_rna(hi.x);
    o0.z = tf32_rna(lo.y); o0.w = tf32_rna(hi.y);
    o1.x = tf32_rna(lo.z); o1.y = tf32_rna(hi.z);
    o1.z = tf32_rna(lo.w); o1.w = tf32_rna(hi.w);
    out[2 * j] = o0; out[2 * j + 1] = o1;
}

// ---------------- mma.sync tf32 GEMM, split-K partials ----------------
// P[z][M,DDIM] = A[M,Kz]*B[DDIM,Kz]^T ; tile 128x64, BK=16, 4-stage cp.async,
// 3 CTAs/SM. Operands K-permuted -> LDS.64 fragment loads.
#define PADK   20
#define ASZ    (128 * PADK)
#define BSZ    (64  * PADK)
#define NSTG   4
#define GSMEM  ((NSTG * (ASZ + BSZ)) * 4)   // 61440 bytes

__global__ void __launch_bounds__(256, 3)
gemm_mma_tf32(const float* __restrict__ A, const float* __restrict__ B,
              float* __restrict__ P, int K, int kc) {
    extern __shared__ float sm[];
    float* smA = sm;
    float* smB = sm + NSTG * ASZ;
    uint32_t sA = smem_u32(smA);
    uint32_t sB = smem_u32(smB);

    const int tid = threadIdx.x;
    const int wid = tid >> 5, lane = tid & 31;
    const int grp = lane >> 2, tig = lane & 3;
    const int wm = (wid & 3) * 32;
    const int wn = (wid >> 2) * 32;

    const int rowA0 = blockIdx.y * 128;
    const int colB0 = blockIdx.x * 64;
    const int kbase = blockIdx.z * kc * 16;
    const int nk = kc;

    const int arow = tid >> 1, ac = (tid & 1) * 8;
    const int brow = tid >> 2, bc = (tid & 3) * 4;
    const float* gA = A + (size_t)(rowA0 + arow) * K + kbase + ac;
    const float* gB = B + (size_t)(colB0 + brow) * K + kbase + bc;
    const uint32_t dA0 = sA + (uint32_t)(arow * PADK + ac) * 4;
    const uint32_t dA1 = dA0 + 16;
    const uint32_t dB0 = sB + (uint32_t)(brow * PADK + bc) * 4;

    float c[2][4][4];
    #pragma unroll
    for (int i = 0; i < 2; i++)
        #pragma unroll
        for (int j = 0; j < 4; j++)
            #pragma unroll
            for (int q = 0; q < 4; q++) c[i][j][q] = 0.0f;

    #pragma unroll
    for (int s = 0; s < NSTG - 1; s++) {
        if (s < nk) {
            CP16(dA0 + (uint32_t)(s * ASZ * 4), gA + (size_t)s * 16);
            CP16(dA1 + (uint32_t)(s * ASZ * 4), gA + (size_t)s * 16 + 4);
            CP16(dB0 + (uint32_t)(s * BSZ * 4), gB + (size_t)s * 16);
        }
        CPCOMMIT();
    }

    int stage = 0;
    for (int kt = 0; kt < nk; kt++) {
        CPWAIT2();
        __syncthreads();

        int pk = kt + NSTG - 1;
        int ps = stage + (NSTG - 1); if (ps >= NSTG) ps -= NSTG;
        if (pk < nk) {
            CP16(dA0 + (uint32_t)(ps * ASZ * 4), gA + (size_t)pk * 16);
            CP16(dA1 + (uint32_t)(ps * ASZ * 4), gA + (size_t)pk * 16 + 4);
            CP16(dB0 + (uint32_t)(ps * BSZ * 4), gB + (size_t)pk * 16);
        }
        CPCOMMIT();

        const float* As_ = smA + stage * ASZ;
        const float* Bs_ = smB + stage * BSZ;

        #pragma unroll
        for (int ka = 0; ka < 2; ka++) {
            int k0 = ka * 8 + 2 * tig;   // permuted: (k=tig, k=tig+4) contiguous
            uint32_t a[2][4], b[4][2];
            #pragma unroll
            for (int ma = 0; ma < 2; ma++) {
                int r = wm + ma * 16 + grp;
                float2 lo = *(const float2*)&As_[r * PADK + k0];
                float2 hi = *(const float2*)&As_[(r + 8) * PADK + k0];
                a[ma][0] = __float_as_uint(lo.x);
                a[ma][1] = __float_as_uint(hi.x);
                a[ma][2] = __float_as_uint(lo.y);
                a[ma][3] = __float_as_uint(hi.y);
            }
            #pragma unroll
            for (int na = 0; na < 4; na++) {
                int r = wn + na * 8 + grp;
                float2 v = *(const float2*)&Bs_[r * PADK + k0];
                b[na][0] = __float_as_uint(v.x);
                b[na][1] = __float_as_uint(v.y);
            }
            #pragma unroll
            for (int ma = 0; ma < 2; ma++)
                #pragma unroll
                for (int na = 0; na < 4; na++)
                    mma_tf32(c[ma][na], a[ma], b[na]);
        }
        if (++stage == NSTG) stage = 0;
    }

    float* Pp = P + (size_t)blockIdx.z * NROI * DDIM;
    #pragma unroll
    for (int ma = 0; ma < 2; ma++) {
        int r0 = rowA0 + wm + ma * 16 + grp;
        #pragma unroll
        for (int na = 0; na < 4; na++) {
            int col = colB0 + wn + na * 8 + tig * 2;
            *(float2*)&Pp[(size_t)r0 * DDIM + col]       = make_float2(c[ma][na][0], c[ma][na][1]);
            *(float2*)&Pp[(size_t)(r0 + 8) * DDIM + col] = make_float2(c[ma][na][2], c[ma][na][3]);
        }
    }
}

// ---------------- split-K reduce + bias + relu (+ optional K-permuted store) --
template<int NP, int PERM, int RND>
__global__ void __launch_bounds__(256)
reduce_kernel(const float* __restrict__ bias, float* __restrict__ C) {
    int i = blockIdx.x * blockDim.x + threadIdx.x;   // 8-block index
    if (i >= NROI * DDIM / 8) return;
    const float4* P = (const float4*)g_P;
    const size_t stride4 = (size_t)NROI * DDIM / 4;
    float v[8];
    {
        float4 lo = P[2 * i], hi = P[2 * i + 1];
        v[0]=lo.x; v[1]=lo.y; v[2]=lo.z; v[3]=lo.w;
        v[4]=hi.x; v[5]=hi.y; v[6]=hi.z; v[7]=hi.w;
    }
    #pragma unroll
    for (int p = 1; p < NP; p++) {
        float4 lo = P[2 * i + 2 * p * stride4 / 2], hi = P[2 * i + 1 + 2 * p * stride4 / 2];
        v[0]+=lo.x; v[1]+=lo.y; v[2]+=lo.z; v[3]+=lo.w;
        v[4]+=hi.x; v[5]+=hi.y; v[6]+=hi.z; v[7]+=hi.w;
    }
    int col = (i * 8) & (DDIM - 1);
    #pragma unroll
    for (int q = 0; q < 8; q++) {
        float r = fmaxf(v[q] + bias[col + q], 0.0f);
        if (RND) r = tf32_rna(r);
        v[q] = r;
    }
    float4 o0, o1;
    if (PERM) {   // positions [v0,v4,v1,v5] [v2,v6,v3,v7]
        o0 = make_float4(v[0], v[4], v[1], v[5]);
        o1 = make_float4(v[2], v[6], v[3], v[7]);
    } else {
        o0 = make_float4(v[0], v[1], v[2], v[3]);
        o1 = make_float4(v[4], v[5], v[6], v[7]);
    }
    ((float4*)C)[2 * i] = o0;
    ((float4*)C)[2 * i + 1] = o1;
}

// ---------------- heads: cls (81) + reg (320), fp32 ----------------
__global__ void __launch_bounds__(256)
heads_kernel(const float* __restrict__ Z,
             const float* __restrict__ Wc, const float* __restrict__ bc,
             const float* __restrict__ Wr, const float* __restrict__ br,
             float* __restrict__ out) {
    __shared__ float zs[8][DDIM];
    int m0 = blockIdx.x * 8;
    for (int i = threadIdx.x; i < 8 * DDIM; i += blockDim.x)
        zs[i >> 10][i & 1023] = Z[(size_t)(m0 + (i >> 10)) * DDIM + (i & 1023)];
    __syncthreads();

    for (int n = threadIdx.x; n < NCLS + NREG; n += blockDim.x) {
        const float* w; float bb;
        if (n < NCLS) { w = Wc + (size_t)n * DDIM; bb = bc[n]; }
        else          { w = Wr + (size_t)(n - NCLS) * DDIM; bb = br[n - NCLS]; }
        float acc[8];
        #pragma unroll
        for (int r = 0; r < 8; r++) acc[r] = bb;
        for (int k = 0; k < DDIM; k += 4) {
            float4 wv = *(const float4*)(w + k);
            #pragma unroll
            for (int r = 0; r < 8; r++) {
                acc[r] = fmaf(zs[r][k + 0], wv.x, acc[r]);
                acc[r] = fmaf(zs[r][k + 1], wv.y, acc[r]);
                acc[r] = fmaf(zs[r][k + 2], wv.z, acc[r]);
                acc[r] = fmaf(zs[r][k + 3], wv.w, acc[r]);
            }
        }
        #pragma unroll
        for (int r = 0; r < 8; r++) {
            int m = m0 + r;
            if (n < NCLS) out[(size_t)m * NCLS + n] = acc[r];
            else out[(size_t)NROI * NCLS + (size_t)m * NREG + (n - NCLS)] = acc[r];
        }
    }
}

// ---------------- launch ----------------
extern "C" void kernel_launch(void* const* d_in, const int* in_sizes, int n_in,
                              void* d_out, int out_size) {
    const float* f2   = (const float*)d_in[0];
    const float* f3   = (const float*)d_in[1];
    const float* f4   = (const float*)d_in[2];
    const float* f5   = (const float*)d_in[3];
    const float* rois = (const float*)d_in[4];
    const float* W1   = (const float*)d_in[5];
    const float* b1   = (const float*)d_in[6];
    const float* W2   = (const float*)d_in[7];
    const float* b2   = (const float*)d_in[8];
    const float* Wc   = (const float*)d_in[9];
    const float* bc   = (const float*)d_in[10];
    const float* Wr   = (const float*)d_in[11];
    const float* br   = (const float*)d_in[12];
    float* out = (float*)d_out;

    float *X, *Y, *Z, *W1r, *W2r, *Pb;
    cudaGetSymbolAddress((void**)&X, g_X);
    cudaGetSymbolAddress((void**)&Y, g_Y);
    cudaGetSymbolAddress((void**)&Z, g_Z);
    cudaGetSymbolAddress((void**)&W1r, g_W1r);
    cudaGetSymbolAddress((void**)&W2r, g_W2r);
    cudaGetSymbolAddress((void**)&Pb, g_P);

    cudaFuncSetAttribute(gemm_mma_tf32, cudaFuncAttributeMaxDynamicSharedMemorySize, GSMEM);

    roi_prep_kernel<<<(NROI + 255) / 256, 256>>>(rois);

    int total = NROI * (CH / 8) * NPIX;
    roi_align_kernel<<<(total + 255) / 256, 256>>>(f2, f3, f4, f5);

    round_all_kernel<<<(N8W1 + N8W2 + 255) / 256, 256>>>((const float4*)W1,
                                                         (const float4*)W2);

    int nred = NROI * DDIM / 8;
    // fc1: K=12544, 784 BK-iters, 196 per split (KS1=4)
    gemm_mma_tf32<<<dim3(DDIM / 64, NROI / 128, KS1), 256, GSMEM>>>(X, W1r, Pb, FDIM, 196);
    reduce_kernel<KS1, 1, 1><<<(nred + 255) / 256, 256>>>(b1, Y);   // permuted (fc2's K)
    // fc2: K=1024, 64 BK-iters, 32 per split (KS2=2)
    gemm_mma_tf32<<<dim3(DDIM / 64, NROI / 128, KS2), 256, GSMEM>>>(Y, W2r, Pb, DDIM, 32);
    reduce_kernel<KS2, 0, 0><<<(nred + 255) / 256, 256>>>(b2, Z);   // natural

    heads_kernel<<<NROI / 8, 256>>>(Z, Wc, bc, Wr, br, out);
}

// round 7
// speedup vs baseline: 1.1300x; 1.1300x over previous
#include <cuda_runtime.h>
#include <cstdint>
#include <math.h>

// ---------------- problem constants ----------------
#define NBS   2
#define NR    512
#define NROI  (NBS*NR)          // 1024
#define CH    256
#define OUTS  7
#define NPIX  (OUTS*OUTS)       // 49
#define FDIM  (CH*NPIX)         // 12544
#define DDIM  1024
#define NCLS  81
#define NREG  320
#define KS1   4                 // split-K for fc1
#define KS2   2                 // split-K for fc2

// ---------------- device scratch ----------------
__device__ float g_X[(size_t)NROI * FDIM];      // pooled features (tf32-rounded)
__device__ float g_Y[(size_t)NROI * DDIM];      // fc1 out (tf32-rounded)
__device__ float g_Z[(size_t)NROI * DDIM];      // fc2 out
__device__ float g_W1r[(size_t)DDIM * FDIM];    // tf32 W1
__device__ float g_W2r[(size_t)DDIM * DDIM];    // tf32 W2
__device__ float g_P[(size_t)KS1 * NROI * DDIM]; // split-K partials (16MB)
__device__ int   g_lvl[NROI];
__device__ float g_meta[NROI * 4];

// ---------------- helpers ----------------
__device__ __forceinline__ float tf32_rna(float x) {
    uint32_t r; asm("cvt.rna.tf32.f32 %0, %1;" : "=r"(r) : "f"(x));
    return __uint_as_float(r);
}
__device__ __forceinline__ uint32_t smem_u32(const void* p) {
    uint32_t a;
    asm("{ .reg .u64 t; cvta.to.shared.u64 t, %1; cvt.u32.u64 %0, t; }" : "=r"(a) : "l"(p));
    return a;
}
#define CP16(dst, src) \
    asm volatile("cp.async.cg.shared.global [%0], [%1], 16;" :: "r"(dst), "l"(src) : "memory")
#define CPCOMMIT() asm volatile("cp.async.commit_group;" ::: "memory")
#define CPWAIT3()  asm volatile("cp.async.wait_group 3;" ::: "memory")

__device__ __forceinline__ void mma_tf32(float c[4], const uint32_t a[4], const uint32_t b[2]) {
    asm volatile(
        "mma.sync.aligned.m16n8k8.row.col.f32.tf32.tf32.f32 "
        "{%0,%1,%2,%3}, {%4,%5,%6,%7}, {%8,%9}, {%0,%1,%2,%3};"
        : "+f"(c[0]), "+f"(c[1]), "+f"(c[2]), "+f"(c[3])
        : "r"(a[0]), "r"(a[1]), "r"(a[2]), "r"(a[3]), "r"(b[0]), "r"(b[1]));
}

// ---------------- roi prep ----------------
__global__ void roi_prep_kernel(const float* __restrict__ rois) {
    int i = blockIdx.x * blockDim.x + threadIdx.x;
    if (i >= NROI) return;
    float x1 = rois[i * 4 + 0], y1 = rois[i * 4 + 1];
    float x2 = rois[i * 4 + 2], y2 = rois[i * 4 + 3];
    float w = x2 - x1, h = y2 - y1;
    float lv = floorf(4.0f + log2f(sqrtf(w * h) / 224.0f + 1e-6f));
    int li = (int)lv - 2;
    g_lvl[i] = li;
    int lic = li < 0 ? 0 : (li > 3 ? 3 : li);
    float scale = 1.0f / (float)(4 << lic);
    float x1s = x1 * scale, y1s = y1 * scale;
    float rw = fmaxf(x2 * scale - x1s, 1.0f);
    float rh = fmaxf(y2 * scale - y1s, 1.0f);
    g_meta[i * 4 + 0] = x1s;
    g_meta[i * 4 + 1] = y1s;
    g_meta[i * 4 + 2] = rw / (float)OUTS;
    g_meta[i * 4 + 3] = rh / (float)OUTS;
}

// ---------------- roi align: 8 channels/thread, branch-free gathers ----------
__global__ void __launch_bounds__(256)
roi_align_kernel(const float* __restrict__ f2, const float* __restrict__ f3,
                 const float* __restrict__ f4, const float* __restrict__ f5) {
    int idx = blockIdx.x * blockDim.x + threadIdx.x;
    if (idx >= NROI * (CH / 8) * NPIX) return;
    int n   = idx / ((CH / 8) * NPIX);
    int rem = idx - n * ((CH / 8) * NPIX);
    int c8  = rem / NPIX;
    int p   = rem - c8 * NPIX;
    int c0  = c8 * 8;

    size_t obase = (size_t)n * FDIM + (size_t)c0 * NPIX + p;

    int li = g_lvl[n];
    if (li < 0 || li > 3) {
        #pragma unroll
        for (int c = 0; c < 8; c++) g_X[obase + (size_t)c * NPIX] = 0.0f;
        return;
    }

    int ph = p / OUTS, pw = p - ph * OUTS;
    const float* f; int H;
    if      (li == 0) { f = f2; H = 200; }
    else if (li == 1) { f = f3; H = 100; }
    else if (li == 2) { f = f4; H = 50;  }
    else              { f = f5; H = 25;  }
    int W = H;
    int HW = H * W;
    int b = (n >= NR) ? 1 : 0;
    const float* base = f + ((size_t)b * CH + c0) * (size_t)HW;

    float x1 = g_meta[n * 4 + 0], y1 = g_meta[n * 4 + 1];
    float bw = g_meta[n * 4 + 2], bh = g_meta[n * 4 + 3];

    int yo0[2], yo1[2]; float lys[2]; float vyf[2];
    int xo0[2], xo1[2]; float lxs[2]; float vxf[2];
    #pragma unroll
    for (int i = 0; i < 2; i++) {
        float y = y1 + ((float)ph + 0.25f + 0.5f * (float)i) * bh;
        vyf[i] = ((y > -1.0f) && (y < (float)H)) ? 1.0f : 0.0f;
        float yc = fminf(fmaxf(y, 0.0f), (float)(H - 1));
        float y0f = floorf(yc);
        int y0 = (int)y0f;
        yo0[i] = y0 * W;
        yo1[i] = min(y0 + 1, H - 1) * W;
        lys[i] = yc - y0f;

        float x = x1 + ((float)pw + 0.25f + 0.5f * (float)i) * bw;
        vxf[i] = ((x > -1.0f) && (x < (float)W)) ? 1.0f : 0.0f;
        float xc = fminf(fmaxf(x, 0.0f), (float)(W - 1));
        float x0f = floorf(xc);
        xo0[i] = (int)x0f;
        xo1[i] = min((int)x0f + 1, W - 1);
        lxs[i] = xc - x0f;
    }

    int   off[16];
    float wgt[16];
    #pragma unroll
    for (int iy = 0; iy < 2; iy++) {
        #pragma unroll
        for (int ix = 0; ix < 2; ix++) {
            float v = vyf[iy] * vxf[ix];
            float ly = lys[iy], lx = lxs[ix];
            int s = (iy * 2 + ix) * 4;
            off[s + 0] = yo0[iy] + xo0[ix]; wgt[s + 0] = v * (1.0f - ly) * (1.0f - lx);
            off[s + 1] = yo0[iy] + xo1[ix]; wgt[s + 1] = v * (1.0f - ly) * lx;
            off[s + 2] = yo1[iy] + xo0[ix]; wgt[s + 2] = v * ly * (1.0f - lx);
            off[s + 3] = yo1[iy] + xo1[ix]; wgt[s + 3] = v * ly * lx;
        }
    }

    #pragma unroll
    for (int c = 0; c < 8; c++) {
        const float* bc = base + (size_t)c * HW;
        float v[16];
        #pragma unroll
        for (int q = 0; q < 16; q++) v[q] = bc[off[q]];
        float acc = 0.0f;
        #pragma unroll
        for (int q = 0; q < 16; q++) acc = fmaf(wgt[q], v[q], acc);
        g_X[obase + (size_t)c * NPIX] = tf32_rna(acc * 0.25f);
    }
}

// ---------------- merged elementwise tf32 round: W1 then W2 ----------------
#define N4W1 (DDIM * FDIM / 4)
#define N4W2 (DDIM * DDIM / 4)
__global__ void round_all_kernel(const float4* __restrict__ w1,
                                 const float4* __restrict__ w2) {
    int i = blockIdx.x * blockDim.x + threadIdx.x;
    const float4* in; float4* out; int j;
    if (i < N4W1) { in = w1; out = (float4*)g_W1r; j = i; }
    else if (i < N4W1 + N4W2) { in = w2; out = (float4*)g_W2r; j = i - N4W1; }
    else return;
    float4 v = in[j];
    v.x = tf32_rna(v.x); v.y = tf32_rna(v.y);
    v.z = tf32_rna(v.z); v.w = tf32_rna(v.w);
    out[j] = v;
}

// ---------------- mma.sync tf32 GEMM, split-K, frag double-buffered ----------
// P[z][M,DDIM] = A[M,Kz]*B[DDIM,Kz]^T ; tile 128x64, BK=16, 6-stage cp.async,
// 2 CTAs/SM, register-level fragment prefetch (incl. cross-stage).
#define PADK   20
#define ASZ    (128 * PADK)
#define BSZ    (64  * PADK)
#define NSTG   6
#define GSMEM  ((NSTG * (ASZ + BSZ)) * 4)   // 92160 bytes

__device__ __forceinline__ void load_frags(const float* __restrict__ As_,
                                           const float* __restrict__ Bs_,
                                           int k0, int wm, int wn, int grp, int tig,
                                           uint32_t a[2][4], uint32_t b[4][2]) {
    #pragma unroll
    for (int ma = 0; ma < 2; ma++) {
        int base = (wm + ma * 16 + grp) * PADK + k0 + tig;
        a[ma][0] = __float_as_uint(As_[base]);
        a[ma][1] = __float_as_uint(As_[base + 8 * PADK]);
        a[ma][2] = __float_as_uint(As_[base + 4]);
        a[ma][3] = __float_as_uint(As_[base + 8 * PADK + 4]);
    }
    #pragma unroll
    for (int na = 0; na < 4; na++) {
        int base = (wn + na * 8 + grp) * PADK + k0 + tig;
        b[na][0] = __float_as_uint(Bs_[base]);
        b[na][1] = __float_as_uint(Bs_[base + 4]);
    }
}

__global__ void __launch_bounds__(256, 2)
gemm_mma_tf32(const float* __restrict__ A, const float* __restrict__ B,
              float* __restrict__ P, int K, int kc) {
    extern __shared__ float sm[];
    float* smA = sm;
    float* smB = sm + NSTG * ASZ;
    uint32_t sA = smem_u32(smA);
    uint32_t sB = smem_u32(smB);

    const int tid = threadIdx.x;
    const int wid = tid >> 5, lane = tid & 31;
    const int grp = lane >> 2, tig = lane & 3;
    const int wm = (wid & 3) * 32;
    const int wn = (wid >> 2) * 32;

    const int rowA0 = blockIdx.y * 128;
    const int colB0 = blockIdx.x * 64;
    const int kbase = blockIdx.z * kc * 16;
    const int nk = kc;

    const int arow = tid >> 1, ac = (tid & 1) * 8;
    const int brow = tid >> 2, bc = (tid & 3) * 4;
    const float* gA = A + (size_t)(rowA0 + arow) * K + kbase + ac;
    const float* gB = B + (size_t)(colB0 + brow) * K + kbase + bc;
    const uint32_t dA0 = sA + (uint32_t)(arow * PADK + ac) * 4;
    const uint32_t dA1 = dA0 + 16;
    const uint32_t dB0 = sB + (uint32_t)(brow * PADK + bc) * 4;

    float c[2][4][4];
    #pragma unroll
    for (int i = 0; i < 2; i++)
        #pragma unroll
        for (int j = 0; j < 4; j++)
            #pragma unroll
            for (int q = 0; q < 4; q++) c[i][j][q] = 0.0f;

    // prologue: fill stages 0..NSTG-2 (5 groups)
    #pragma unroll
    for (int s = 0; s < NSTG - 1; s++) {
        if (s < nk) {
            CP16(dA0 + (uint32_t)(s * ASZ * 4), gA + (size_t)s * 16);
            CP16(dA1 + (uint32_t)(s * ASZ * 4), gA + (size_t)s * 16 + 4);
            CP16(dB0 + (uint32_t)(s * BSZ * 4), gB + (size_t)s * 16);
        }
        CPCOMMIT();
    }

    uint32_t aF[2][2][4], bF[2][4][2];

    // iter 0 head: wait (completes chunks 0..1), sync, preload frags(stage0, ka0)
    CPWAIT3();
    __syncthreads();
    load_frags(smA, smB, 0, wm, wn, grp, tig, aF[0], bF[0]);

    int stage = 0;
    for (int kt = 0; kt < nk; kt++) {
        if (kt > 0) {
            CPWAIT3();          // completes chunks 0..kt+1 (cross-stage prefetch safe)
            __syncthreads();    // all warps done reading stage being overwritten
        }

        int pk = kt + NSTG - 1;
        int ps = stage + (NSTG - 1); if (ps >= NSTG) ps -= NSTG;
        if (pk < nk) {
            CP16(dA0 + (uint32_t)(ps * ASZ * 4), gA + (size_t)pk * 16);
            CP16(dA1 + (uint32_t)(ps * ASZ * 4), gA + (size_t)pk * 16 + 4);
            CP16(dB0 + (uint32_t)(ps * BSZ * 4), gB + (size_t)pk * 16);
        }
        CPCOMMIT();

        int nstage = (stage + 1 == NSTG) ? 0 : stage + 1;
        const float* As_ = smA + stage * ASZ;
        const float* Bs_ = smB + stage * BSZ;
        const float* Asn = smA + nstage * ASZ;
        const float* Bsn = smB + nstage * BSZ;

        // ka=0: prefetch ka=1 frags, then MMA on current
        load_frags(As_, Bs_, 8, wm, wn, grp, tig, aF[1], bF[1]);
        #pragma unroll
        for (int ma = 0; ma < 2; ma++)
            #pragma unroll
            for (int na = 0; na < 4; na++)
                mma_tf32(c[ma][na], aF[0][ma], bF[0][na]);

        // ka=1: prefetch next stage's ka=0 frags (chunk kt+1 already complete)
        load_frags(Asn, Bsn, 0, wm, wn, grp, tig, aF[0], bF[0]);
        #pragma unroll
        for (int ma = 0; ma < 2; ma++)
            #pragma unroll
            for (int na = 0; na < 4; na++)
                mma_tf32(c[ma][na], aF[1][ma], bF[1][na]);

        stage = nstage;
    }

    float* Pp = P + (size_t)blockIdx.z * NROI * DDIM;
    #pragma unroll
    for (int ma = 0; ma < 2; ma++) {
        int r0 = rowA0 + wm + ma * 16 + grp;
        #pragma unroll
        for (int na = 0; na < 4; na++) {
            int col = colB0 + wn + na * 8 + tig * 2;
            *(float2*)&Pp[(size_t)r0 * DDIM + col]       = make_float2(c[ma][na][0], c[ma][na][1]);
            *(float2*)&Pp[(size_t)(r0 + 8) * DDIM + col] = make_float2(c[ma][na][2], c[ma][na][3]);
        }
    }
}

// ---------------- split-K reduce + bias + relu (+ tf32 round) ----------------
template<int NP, int RND>
__global__ void __launch_bounds__(256)
reduce_kernel(const float* __restrict__ bias, float* __restrict__ C) {
    int i = blockIdx.x * blockDim.x + threadIdx.x;   // float4 index
    if (i >= NROI * DDIM / 4) return;
    const float4* P = (const float4*)g_P;
    const size_t stride = (size_t)NROI * DDIM / 4;
    float4 v = P[i];
    #pragma unroll
    for (int p = 1; p < NP; p++) {
        float4 u = P[i + p * stride];
        v.x += u.x; v.y += u.y; v.z += u.z; v.w += u.w;
    }
    int col = (i * 4) & (DDIM - 1);
    float4 bv = *(const float4*)&bias[col];
    float4 r;
    r.x = fmaxf(v.x + bv.x, 0.0f);
    r.y = fmaxf(v.y + bv.y, 0.0f);
    r.z = fmaxf(v.z + bv.z, 0.0f);
    r.w = fmaxf(v.w + bv.w, 0.0f);
    if (RND) { r.x = tf32_rna(r.x); r.y = tf32_rna(r.y);
               r.z = tf32_rna(r.z); r.w = tf32_rna(r.w); }
    ((float4*)C)[i] = r;
}

// ---------------- heads: cls (81) + reg (320), fp32 ----------------
__global__ void __launch_bounds__(256)
heads_kernel(const float* __restrict__ Z,
             const float* __restrict__ Wc, const float* __restrict__ bc,
             const float* __restrict__ Wr, const float* __restrict__ br,
             float* __restrict__ out) {
    __shared__ float zs[8][DDIM];
    int m0 = blockIdx.x * 8;
    for (int i = threadIdx.x; i < 8 * DDIM; i += blockDim.x)
        zs[i >> 10][i & 1023] = Z[(size_t)(m0 + (i >> 10)) * DDIM + (i & 1023)];
    __syncthreads();

    for (int n = threadIdx.x; n < NCLS + NREG; n += blockDim.x) {
        const float* w; float bb;
        if (n < NCLS) { w = Wc + (size_t)n * DDIM; bb = bc[n]; }
        else          { w = Wr + (size_t)(n - NCLS) * DDIM; bb = br[n - NCLS]; }
        float acc[8];
        #pragma unroll
        for (int r = 0; r < 8; r++) acc[r] = bb;
        for (int k = 0; k < DDIM; k += 4) {
            float4 wv = *(const float4*)(w + k);
            #pragma unroll
            for (int r = 0; r < 8; r++) {
                acc[r] = fmaf(zs[r][k + 0], wv.x, acc[r]);
                acc[r] = fmaf(zs[r][k + 1], wv.y, acc[r]);
                acc[r] = fmaf(zs[r][k + 2], wv.z, acc[r]);
                acc[r] = fmaf(zs[r][k + 3], wv.w, acc[r]);
            }
        }
        #pragma unroll
        for (int r = 0; r < 8; r++) {
            int m = m0 + r;
            if (n < NCLS) out[(size_t)m * NCLS + n] = acc[r];
            else out[(size_t)NROI * NCLS + (size_t)m * NREG + (n - NCLS)] = acc[r];
        }
    }
}

// ---------------- launch ----------------
extern "C" void kernel_launch(void* const* d_in, const int* in_sizes, int n_in,
                              void* d_out, int out_size) {
    const float* f2   = (const float*)d_in[0];
    const float* f3   = (const float*)d_in[1];
    const float* f4   = (const float*)d_in[2];
    const float* f5   = (const float*)d_in[3];
    const float* rois = (const float*)d_in[4];
    const float* W1   = (const float*)d_in[5];
    const float* b1   = (const float*)d_in[6];
    const float* W2   = (const float*)d_in[7];
    const float* b2   = (const float*)d_in[8];
    const float* Wc   = (const float*)d_in[9];
    const float* bc   = (const float*)d_in[10];
    const float* Wr   = (const float*)d_in[11];
    const float* br   = (const float*)d_in[12];
    float* out = (float*)d_out;

    float *X, *Y, *Z, *W1r, *W2r, *Pb;
    cudaGetSymbolAddress((void**)&X, g_X);
    cudaGetSymbolAddress((void**)&Y, g_Y);
    cudaGetSymbolAddress((void**)&Z, g_Z);
    cudaGetSymbolAddress((void**)&W1r, g_W1r);
    cudaGetSymbolAddress((void**)&W2r, g_W2r);
    cudaGetSymbolAddress((void**)&Pb, g_P);

    cudaFuncSetAttribute(gemm_mma_tf32, cudaFuncAttributeMaxDynamicSharedMemorySize, GSMEM);

    roi_prep_kernel<<<(NROI + 255) / 256, 256>>>(rois);

    int total = NROI * (CH / 8) * NPIX;
    roi_align_kernel<<<(total + 255) / 256, 256>>>(f2, f3, f4, f5);

    round_all_kernel<<<(N4W1 + N4W2 + 255) / 256, 256>>>((const float4*)W1,
                                                         (const float4*)W2);

    int nred = NROI * DDIM / 4;
    // fc1: K=12544, 784 BK-iters, 196 per split (KS1=4)
    gemm_mma_tf32<<<dim3(DDIM / 64, NROI / 128, KS1), 256, GSMEM>>>(X, W1r, Pb, FDIM, 196);
    reduce_kernel<KS1, 1><<<(nred + 255) / 256, 256>>>(b1, Y);
    // fc2: K=1024, 64 BK-iters, 32 per split (KS2=2)
    gemm_mma_tf32<<<dim3(DDIM / 64, NROI / 128, KS2), 256, GSMEM>>>(Y, W2r, Pb, DDIM, 32);
    reduce_kernel<KS2, 0><<<(nred + 255) / 256, 256>>>(b2, Z);

    heads_kernel<<<NROI / 8, 256>>>(Z, Wc, bc, Wr, br, out);
}